// round 14
// baseline (speedup 1.0000x reference)
#include <cuda_runtime.h>
#include <cuda_fp16.h>
#include <cstdint>

#define B_   256
#define CIN  128
#define NPTS 1024
#define M_   1023
#define COUT 64
#define M3   3069
#define OUTW 1024
#define NTILES 2048          // m-tiles of 128 rows: 8 per batch
#define GRID_P 148
#define KMAX  14             // ceil(2048/148)

// ---------------- scratch (__device__ globals) ----------------------------
__device__ __half g_th[(size_t)B_ * NPTS * CIN];       // [b][n][c] fp16
__device__ __align__(256) unsigned char g_Wsw[3 * 16384]; // W fp16 image
__device__ int g_idx_is64;

// ---------------- PTX helpers ---------------------------------------------
__device__ __forceinline__ uint32_t smem_u32(const void* p) {
    uint32_t a;
    asm("{ .reg .u64 t; cvta.to.shared.u64 t, %1; cvt.u32.u64 %0, t; }"
        : "=r"(a) : "l"(p));
    return a;
}
#define CP_ASYNC16(dst, src) \
    asm volatile("cp.async.cg.shared.global [%0], [%1], 16;" :: "r"(dst), "l"(src) : "memory")
#define CP_COMMIT() asm volatile("cp.async.commit_group;" ::: "memory")
#define CP_WAIT0()  asm volatile("cp.async.wait_group 0;" ::: "memory")
#define CP_WAIT1()  asm volatile("cp.async.wait_group 1;" ::: "memory")

#define LDSM_X4(r0, r1, r2, r3, addr) \
    asm volatile("ldmatrix.sync.aligned.m8n8.x4.shared.b16 {%0,%1,%2,%3}, [%4];" \
        : "=r"(r0), "=r"(r1), "=r"(r2), "=r"(r3) : "r"(addr))

#define MMA_F16(d, a, b0, b1) \
    asm volatile("mma.sync.aligned.m16n8k16.row.col.f32.f16.f16.f32 " \
        "{%0,%1,%2,%3}, {%4,%5,%6,%7}, {%8,%9}, {%0,%1,%2,%3};" \
        : "+f"((d)[0]), "+f"((d)[1]), "+f"((d)[2]), "+f"((d)[3]) \
        : "r"((a)[0]), "r"((a)[1]), "r"((a)[2]), "r"((a)[3]), "r"(b0), "r"(b1))

// ---------------- kernel 0: index dtype detection --------------------------
__global__ void detect_kernel(const int* __restrict__ idx32) {
    __shared__ int any_nz;
    if (threadIdx.x == 0) any_nz = 0;
    __syncthreads();
    int nz = 0;
    for (int i = threadIdx.x; i < 1024; i += blockDim.x)
        nz |= (idx32[2 * i + 1] != 0);
    if (nz) atomicOr(&any_nz, 1);
    __syncthreads();
    if (threadIdx.x == 0) g_idx_is64 = any_nz ? 0 : 1;
}

// ---------------- kernel 1: transpose + fp16 convert (64x64 tiles) ---------
// reads float4 (full 128B rows), writes 2x16B fp16 per thread (full sectors)
__global__ void transpose_half_kernel(const float* __restrict__ trees) {
    __shared__ float tile[64][68];
    int b = blockIdx.z;
    int nBase = blockIdx.x * 64;
    int cBase = blockIdx.y * 64;
    int t = threadIdx.x;
    const float* src = trees + ((size_t)b * CIN + cBase) * NPTS + nBase;
    #pragma unroll
    for (int p = 0; p < 4; p++) {
        int linear = p * 256 + t;          // 0..1023
        int c  = linear >> 4;              // 64 c-rows
        int n4 = linear & 15;              // 16 float4 per row
        float4 v = *(const float4*)(src + (size_t)c * NPTS + n4 * 4);
        *(float4*)&tile[c][n4 * 4] = v;
    }
    __syncthreads();
    int n = t >> 2;                        // 0..63
    int q = t & 3;                         // quarter: 16 c each
    __half* dst = g_th + ((size_t)(b * NPTS) + nBase + n) * CIN + cBase + q * 16;
    __half tmp[16];
    #pragma unroll
    for (int i = 0; i < 16; i++)
        tmp[i] = __float2half(tile[q * 16 + i][n]);
    *(uint4*)(dst)     = *(uint4*)tmp;
    *(uint4*)(dst + 8) = *(uint4*)(tmp + 8);
}

// ---------------- kernel 2: W -> fp16 swizzled image -----------------------
// byte layout: tap*16384 + o*256 + swz(g,o)*16 + (c&7)*2
__global__ void wprep_kernel(const float* __restrict__ W) {
    int i = blockIdx.x * 256 + threadIdx.x;
    if (i >= 3 * 64 * 128) return;
    int c = i & 127;
    int o = (i >> 7) & 63;
    int k = i >> 13;
    float v = W[(o * CIN + c) * 3 + k];
    int g = c >> 3;
    uint32_t swz = (g & 8) | ((g & 7) ^ (o & 7));
    uint32_t off = k * 16384 + o * 256 + (swz << 4) + (c & 7) * 2;
    *(__half*)(g_Wsw + off) = __float2half(v);
}

// ---------------- kernel 3: persistent gather + HMMA fp16 GEMM -------------
// grid 148, 512 threads: 16 warps = 2 k-groups x (4m x 2n), warp tile 32m x 32o.
// WARP-PRIVATE gather: each warp loads only the 32 rows x 128B c-half it
// consumes (lane = 1 row, 8x16B cp.async). NO block barriers in the mainloop;
// each warp syncs only on its own cp.async groups. 2-slot warp-private ring.
// Block barriers only at the per-tile k-group reduction (2 per 3 stages).
#define SM_W    0
#define SM_IDX  49152
#define SM_STAG 61440
#define SM_A    94208
#define SMEM_TOTAL (94208 + 2 * 65536)   // 225280

__global__ void __launch_bounds__(512, 1) convtree_persist_kernel(
    const void* __restrict__ indexes_raw,
    const float* __restrict__ bias,
    float* __restrict__ out)
{
    extern __shared__ char smem[];
    const uint32_t sb = smem_u32(smem);
    const int tid  = threadIdx.x;
    const int lane = tid & 31;
    const int w    = tid >> 5;
    const int kg   = w >> 3;          // k-group 0/1 (c-half)
    const int wm   = w & 3;           // m-group: rows wm*32 .. wm*32+31
    const int wn   = (w >> 2) & 1;    // n-group: o wn*32 .. wn*32+31
    const int cta  = blockIdx.x;
    const int is64 = g_idx_is64;
    const int* i32 = (const int*)indexes_raw;
    const long long* i64 = (const long long*)indexes_raw;
    uint16_t* sidx = (uint16_t*)(smem + SM_IDX);

    const int K = (NTILES - cta + GRID_P - 1) / GRID_P;
    const int S = 3 * K;

    // ---- W image, loaded once per CTA (pre-swizzled, linear copy) ----
    for (int i = tid; i < 3072; i += 512)
        CP_ASYNC16(sb + SM_W + i * 16, (const char*)g_Wsw + i * 16);
    CP_COMMIT();

    // ---- preload ALL gather indices for this CTA's tiles (uint16) ----
    for (int e = tid; e < K * 384; e += 512) {
        int j = e / 384, i2 = e - j * 384;
        int tile = cta + j * GRID_P;
        int b = tile >> 3, m0 = (tile & 7) << 7;
        int gm = m0 + i2 / 3;
        int v = 0;
        if (gm < M_) {
            int flat = b * M3 + 3 * gm + (i2 % 3);
            v = is64 ? (int)i64[flat] : i32[flat];
        }
        sidx[e] = (uint16_t)(v & (NPTS - 1));
    }

    // ---- per-thread bias values (used by k-group 0 in epilogue) ----
    const int ocl = (lane & 3) * 2;
    float bv[2][2][2];
    #pragma unroll
    for (int ntp = 0; ntp < 2; ntp++)
        #pragma unroll
        for (int sub = 0; sub < 2; sub++) {
            int o = wn * 32 + ntp * 16 + sub * 8 + ocl;
            bv[ntp][sub][0] = bias[o];
            bv[ntp][sub][1] = bias[o + 1];
        }
    CP_WAIT0();
    __syncthreads();   // W image + sidx visible; cp.async group count clean

    // warp-private stage loader: stage s = (tile s/3, tap s%3), slot s&1.
    // lane loads one full row's c-half: 8 x 16B cp.async.
    const int myrow = wm * 32 + lane;
    auto load_stage = [&](int s) {
        int j = s / 3, tap = s - 3 * j;
        int tile = cta + j * GRID_P;
        int b = tile >> 3;
        int n = sidx[j * 384 + myrow * 3 + tap];
        const char* src = (const char*)g_th
                        + ((((size_t)(b << 10)) + n) << 8) + (kg << 7);
        uint32_t dbase = sb + SM_A + ((s & 1) << 16) + (w << 12) + (lane << 7);
        #pragma unroll
        for (int q = 0; q < 8; q++)
            CP_ASYNC16(dbase + ((q ^ (lane & 7)) << 4), src + q * 16);
        CP_COMMIT();
    };

    load_stage(0);

    float acc[2][2][2][4];   // [mt][ntp][sub][quad]
    #pragma unroll
    for (int a = 0; a < 2; a++)
        #pragma unroll
        for (int b2 = 0; b2 < 2; b2++)
            #pragma unroll
            for (int c = 0; c < 2; c++)
                #pragma unroll
                for (int d = 0; d < 4; d++) acc[a][b2][c][d] = 0.0f;

    const int ag = lane >> 4;
    const int bg = (lane >> 3) & 1;
    const int brow_base = wn * 32 + ((lane >> 4) << 3) + (lane & 7);
    const int l7 = lane & 7;
    const int rl = lane >> 2;
    float* stag = (float*)(smem + SM_STAG);   // [o][m] 64x128

    for (int s = 0; s < S; s++) {
        if (s + 1 < S) { load_stage(s + 1); CP_WAIT1(); }
        else CP_WAIT0();
        // no __syncthreads: this warp's slot data is warp-private

        const int tap = s - 3 * (s / 3);
        const uint32_t awarp = sb + SM_A + ((s & 1) << 16) + (w << 12)
                             + (lane & 15) * 128;
        const uint32_t wtap = sb + SM_W + tap * 16384;

        // burst 8 independent LDSM, then 16 MMA (x2)
        #pragma unroll
        for (int kp = 0; kp < 2; kp++) {
            uint32_t af[2][2][4];   // [ks][mt]
            uint32_t bf[2][2][4];   // [ks][ntp]
            #pragma unroll
            for (int ks = 0; ks < 2; ks++) {
                int ql = (kp * 2 + ks) * 2 + ag;        // local chunk 0..7
                uint32_t swA = (uint32_t)(ql ^ l7);
                LDSM_X4(af[ks][0][0], af[ks][0][1], af[ks][0][2], af[ks][0][3],
                        awarp + (swA << 4));
                LDSM_X4(af[ks][1][0], af[ks][1][1], af[ks][1][2], af[ks][1][3],
                        awarp + 2048 + (swA << 4));
                int gb = kg * 8 + (kp * 2 + ks) * 2 + bg;
                uint32_t swB = (uint32_t)((gb & 8) | ((gb & 7) ^ l7));
                LDSM_X4(bf[ks][0][0], bf[ks][0][1], bf[ks][0][2], bf[ks][0][3],
                        wtap + brow_base * 256 + (swB << 4));
                LDSM_X4(bf[ks][1][0], bf[ks][1][1], bf[ks][1][2], bf[ks][1][3],
                        wtap + (brow_base + 16) * 256 + (swB << 4));
            }
            #pragma unroll
            for (int ks = 0; ks < 2; ks++) {
                #pragma unroll
                for (int ntp = 0; ntp < 2; ntp++) {
                    MMA_F16(acc[0][ntp][0], af[ks][0], bf[ks][ntp][0], bf[ks][ntp][1]);
                    MMA_F16(acc[0][ntp][1], af[ks][0], bf[ks][ntp][2], bf[ks][ntp][3]);
                    MMA_F16(acc[1][ntp][0], af[ks][1], bf[ks][ntp][0], bf[ks][ntp][1]);
                    MMA_F16(acc[1][ntp][1], af[ks][1], bf[ks][ntp][2], bf[ks][ntp][3]);
                }
            }
        }

        // ---- after tap 2: kg1 stages partials, kg0 reduces + stores ----
        if (tap == 2) {
            int tile = cta + (s / 3) * GRID_P;
            int b = tile >> 3, m0 = (tile & 7) << 7;
            float* ob = out + (((size_t)b * COUT) << 10);
            __syncthreads();   // stag WAR: kg0 done reading previous tile
            if (kg == 1) {
                #pragma unroll
                for (int mt = 0; mt < 2; mt++) {
                    int m = wm * 32 + mt * 16 + rl;
                    #pragma unroll
                    for (int ntp = 0; ntp < 2; ntp++)
                        #pragma unroll
                        for (int sub = 0; sub < 2; sub++) {
                            int o = wn * 32 + ntp * 16 + sub * 8 + ocl;
                            float* q = &acc[mt][ntp][sub][0];
                            stag[o * 128 + m]           = q[0];
                            stag[(o + 1) * 128 + m]     = q[1];
                            stag[o * 128 + m + 8]       = q[2];
                            stag[(o + 1) * 128 + m + 8] = q[3];
                            q[0] = q[1] = q[2] = q[3] = 0.0f;
                        }
                }
                // zero column m=0 (only tiles that own m0 == 0)
                if (m0 == 0 && lane < 8) {
                    int o = (w - 8) * 8 + lane;
                    ob[(size_t)o << 10] = 0.0f;
                }
            }
            __syncthreads();   // kg1 partials visible to kg0
            if (kg == 0) {
                #pragma unroll
                for (int mt = 0; mt < 2; mt++) {
                    int m = wm * 32 + mt * 16 + rl;
                    int gmb = m0 + m;
                    #pragma unroll
                    for (int ntp = 0; ntp < 2; ntp++)
                        #pragma unroll
                        for (int sub = 0; sub < 2; sub++) {
                            int o = wn * 32 + ntp * 16 + sub * 8 + ocl;
                            float* p0 = ob + (((size_t)o) << 10) + 1;
                            float* p1 = ob + (((size_t)(o + 1)) << 10) + 1;
                            float* q = &acc[mt][ntp][sub][0];
                            float v0 = q[0] + stag[o * 128 + m]           + bv[ntp][sub][0];
                            float v1 = q[1] + stag[(o + 1) * 128 + m]     + bv[ntp][sub][1];
                            float v2 = q[2] + stag[o * 128 + m + 8]       + bv[ntp][sub][0];
                            float v3 = q[3] + stag[(o + 1) * 128 + m + 8] + bv[ntp][sub][1];
                            if (gmb < M_) { p0[gmb] = v0; p1[gmb] = v1; }
                            if (gmb + 8 < M_) { p0[gmb + 8] = v2; p1[gmb + 8] = v3; }
                            q[0] = q[1] = q[2] = q[3] = 0.0f;
                        }
                }
            }
        }
    }
}

// ---------------- kernel 4: optional index tail (mode 1/2 only) ------------
__global__ void tail_kernel(const void* __restrict__ idx_raw,
                            float* __restrict__ out, int mode) {
    int i = blockIdx.x * 256 + threadIdx.x;
    const int is64 = g_idx_is64;
    const int* i32 = (const int*)idx_raw;
    const long long* i64 = (const long long*)idx_raw;
    if (i < B_ * M3) {
        long long v = is64 ? i64[i] : (long long)i32[i];
        if (mode == 1) {
            out[(size_t)B_ * COUT * OUTW + i] = (float)v;
        } else if (mode == 2) {
            ((long long*)out)[(size_t)(B_ * COUT * OUTW) / 2 + i] = v;
        }
    }
}

// ---------------------------------------------------------------------------
extern "C" void kernel_launch(void* const* d_in, const int* in_sizes, int n_in,
                              void* d_out, int out_size) {
    const float* trees = nullptr;
    const void* indexes = nullptr;
    const float* W = nullptr;
    const float* bias = nullptr;
    for (int i = 0; i < n_in; i++) {
        switch (in_sizes[i]) {
            case B_ * CIN * NPTS: trees   = (const float*)d_in[i]; break;
            case B_ * M3:         indexes = d_in[i];               break;
            case COUT * CIN * 3:  W       = (const float*)d_in[i]; break;
            case COUT:            bias    = (const float*)d_in[i]; break;
        }
    }
    float* out = (float*)d_out;

    cudaFuncSetAttribute(convtree_persist_kernel,
                         cudaFuncAttributeMaxDynamicSharedMemorySize, SMEM_TOTAL);

    detect_kernel<<<1, 256>>>((const int*)indexes);
    transpose_half_kernel<<<dim3(NPTS / 64, CIN / 64, B_), 256>>>(trees);
    wprep_kernel<<<(3 * 64 * 128 + 255) / 256, 256>>>(W);
    convtree_persist_kernel<<<GRID_P, 512, SMEM_TOTAL>>>(indexes, bias, out);

    long long R = (long long)B_ * COUT * OUTW;
    long long I = (long long)B_ * M3;
    int mode = 0;
    if ((long long)out_size >= R + 2 * I)      mode = 2;
    else if ((long long)out_size >= R + I)     mode = 1;
    if (mode != 0)
        tail_kernel<<<(B_ * M3 + 255) / 256, 256>>>(indexes, out, mode);
}

// round 16
// speedup vs baseline: 1.4280x; 1.4280x over previous
#include <cuda_runtime.h>
#include <cuda_fp16.h>
#include <cstdint>

#define B_   256
#define CIN  128
#define NPTS 1024
#define M_   1023
#define COUT 64
#define M3   3069
#define OUTW 1024
#define NTILES 2048          // m-tiles of 128 rows: 8 per batch
#define GRID_P 148
#define NSLOT 4
#define KMAX  14             // ceil(2048/148)

// ---------------- scratch (__device__ globals) ----------------------------
__device__ __half g_th[(size_t)B_ * NPTS * CIN];       // [b][n][c] fp16
__device__ __align__(256) unsigned char g_Wsw[3 * 16384]; // W fp16 image
__device__ int g_idx_is64;

// ---------------- PTX helpers ---------------------------------------------
__device__ __forceinline__ uint32_t smem_u32(const void* p) {
    uint32_t a;
    asm("{ .reg .u64 t; cvta.to.shared.u64 t, %1; cvt.u32.u64 %0, t; }"
        : "=r"(a) : "l"(p));
    return a;
}
#define CP_ASYNC16(dst, src) \
    asm volatile("cp.async.cg.shared.global [%0], [%1], 16;" :: "r"(dst), "l"(src) : "memory")
#define CP_COMMIT() asm volatile("cp.async.commit_group;" ::: "memory")
#define CP_WAIT0()  asm volatile("cp.async.wait_group 0;" ::: "memory")
#define CP_WAIT1()  asm volatile("cp.async.wait_group 1;" ::: "memory")
#define CP_WAIT2()  asm volatile("cp.async.wait_group 2;" ::: "memory")
#define BAR_SYNC(id) asm volatile("bar.sync %0, 256;" :: "r"(id) : "memory")

#define LDSM_X4(r0, r1, r2, r3, addr) \
    asm volatile("ldmatrix.sync.aligned.m8n8.x4.shared.b16 {%0,%1,%2,%3}, [%4];" \
        : "=r"(r0), "=r"(r1), "=r"(r2), "=r"(r3) : "r"(addr))

#define MMA_F16(d, a, b0, b1) \
    asm volatile("mma.sync.aligned.m16n8k16.row.col.f32.f16.f16.f32 " \
        "{%0,%1,%2,%3}, {%4,%5,%6,%7}, {%8,%9}, {%0,%1,%2,%3};" \
        : "+f"((d)[0]), "+f"((d)[1]), "+f"((d)[2]), "+f"((d)[3]) \
        : "r"((a)[0]), "r"((a)[1]), "r"((a)[2]), "r"((a)[3]), "r"(b0), "r"(b1))

// ---------------- kernel 0: index dtype detection --------------------------
__global__ void detect_kernel(const int* __restrict__ idx32) {
    __shared__ int any_nz;
    if (threadIdx.x == 0) any_nz = 0;
    __syncthreads();
    int nz = 0;
    for (int i = threadIdx.x; i < 1024; i += blockDim.x)
        nz |= (idx32[2 * i + 1] != 0);
    if (nz) atomicOr(&any_nz, 1);
    __syncthreads();
    if (threadIdx.x == 0) g_idx_is64 = any_nz ? 0 : 1;
}

// ---------------- kernel 1: transpose + fp16 convert (64x64 tiles) ---------
// reads float4 (full 128B rows), writes 2x16B fp16 per thread (full sectors)
__global__ void transpose_half_kernel(const float* __restrict__ trees) {
    __shared__ float tile[64][68];
    int b = blockIdx.z;
    int nBase = blockIdx.x * 64;
    int cBase = blockIdx.y * 64;
    int t = threadIdx.x;
    const float* src = trees + ((size_t)b * CIN + cBase) * NPTS + nBase;
    #pragma unroll
    for (int p = 0; p < 4; p++) {
        int linear = p * 256 + t;          // 0..1023
        int c  = linear >> 4;              // 64 c-rows
        int n4 = linear & 15;              // 16 float4 per row
        float4 v = *(const float4*)(src + (size_t)c * NPTS + n4 * 4);
        *(float4*)&tile[c][n4 * 4] = v;
    }
    __syncthreads();
    int n = t >> 2;                        // 0..63
    int q = t & 3;                         // quarter: 16 c each
    __half* dst = g_th + ((size_t)(b * NPTS) + nBase + n) * CIN + cBase + q * 16;
    __half tmp[16];
    #pragma unroll
    for (int i = 0; i < 16; i++)
        tmp[i] = __float2half(tile[q * 16 + i][n]);
    *(uint4*)(dst)     = *(uint4*)tmp;
    *(uint4*)(dst + 8) = *(uint4*)(tmp + 8);
}

// ---------------- kernel 2: W -> fp16 swizzled image -----------------------
// byte layout: tap*16384 + o*256 + swz(g,o)*16 + (c&7)*2
__global__ void wprep_kernel(const float* __restrict__ W) {
    int i = blockIdx.x * 256 + threadIdx.x;
    if (i >= 3 * 64 * 128) return;
    int c = i & 127;
    int o = (i >> 7) & 63;
    int k = i >> 13;
    float v = W[(o * CIN + c) * 3 + k];
    int g = c >> 3;
    uint32_t swz = (g & 8) | ((g & 7) ^ (o & 7));
    uint32_t off = k * 16384 + o * 256 + (swz << 4) + (c & 7) * 2;
    *(__half*)(g_Wsw + off) = __float2half(v);
}

// ---------------- kernel 3: persistent gather + HMMA fp16 GEMM -------------
// grid 148, 512 threads: 16 warps = 2 k-groups x (4m x 2n), warp tile 32m x 32o.
// Stage = 128 rows, split per k-group: kg's 256 threads load the kg c-half
// (16KB) consumed only by kg's warps. Stage-top sync = 256-thread bar.sync
// per k-group (half the skew of a full __syncthreads); k-groups drift freely
// within a tile. 4-slot ring, prefetch distance 3. Full-block sync only at
// the per-tile k-group reduction (2 per 3 stages).
#define SM_W    0
#define SM_IDX  49152
#define SM_STAG 61440
#define SM_A    94208
#define SMEM_TOTAL (94208 + NSLOT * 32768)   // 225280

__global__ void __launch_bounds__(512, 1) convtree_persist_kernel(
    const void* __restrict__ indexes_raw,
    const float* __restrict__ bias,
    float* __restrict__ out)
{
    extern __shared__ char smem[];
    const uint32_t sb = smem_u32(smem);
    const int tid  = threadIdx.x;
    const int lane = tid & 31;
    const int w    = tid >> 5;
    const int kg   = w >> 3;          // k-group 0/1 (c-half)
    const int wm   = w & 3;           // m-group: rows wm*32 .. wm*32+31
    const int wn   = (w >> 2) & 1;    // n-group: o wn*32 .. wn*32+31
    const int cta  = blockIdx.x;
    const int is64 = g_idx_is64;
    const int* i32 = (const int*)indexes_raw;
    const long long* i64 = (const long long*)indexes_raw;
    uint16_t* sidx = (uint16_t*)(smem + SM_IDX);

    const int K = (NTILES - cta + GRID_P - 1) / GRID_P;
    const int S = 3 * K;

    // ---- W image, loaded once per CTA (pre-swizzled, linear copy) ----
    for (int i = tid; i < 3072; i += 512)
        CP_ASYNC16(sb + SM_W + i * 16, (const char*)g_Wsw + i * 16);
    CP_COMMIT();

    // ---- preload ALL gather indices for this CTA's tiles (uint16) ----
    for (int e = tid; e < K * 384; e += 512) {
        int j = e / 384, i2 = e - j * 384;
        int tile = cta + j * GRID_P;
        int b = tile >> 3, m0 = (tile & 7) << 7;
        int gm = m0 + i2 / 3;
        int v = 0;
        if (gm < M_) {
            int flat = b * M3 + 3 * gm + (i2 % 3);
            v = is64 ? (int)i64[flat] : i32[flat];
        }
        sidx[e] = (uint16_t)(v & (NPTS - 1));
    }

    // ---- per-thread bias values (used by k-group 0 in epilogue) ----
    const int ocl = (lane & 3) * 2;
    float bv[2][2][2];
    #pragma unroll
    for (int ntp = 0; ntp < 2; ntp++)
        #pragma unroll
        for (int sub = 0; sub < 2; sub++) {
            int o = wn * 32 + ntp * 16 + sub * 8 + ocl;
            bv[ntp][sub][0] = bias[o];
            bv[ntp][sub][1] = bias[o + 1];
        }
    CP_WAIT0();
    __syncthreads();   // W image + sidx visible; cp.async group count clean

    // kg-private stage loader: kg's 256 threads load the kg c-half of all
    // 128 rows (thread = half-row, 4 x 16B). Ring slot layout:
    // SM_A + slot*32768 + kg*16384 + row*128, chunk swizzle g ^ (row&7).
    auto load_stage = [&](int s) {
        int j = s / 3, tap = s - 3 * j;
        int tile = cta + j * GRID_P;
        int b = tile >> 3;
        int t2 = tid & 255;
        int row = t2 >> 1, half = t2 & 1;
        int n = sidx[j * 384 + row * 3 + tap];
        const char* src = (const char*)g_th
                        + ((((size_t)(b << 10)) + n) << 8) + (kg << 7) + (half << 6);
        uint32_t dbase = sb + SM_A + (s % NSLOT) * 32768 + (kg << 14) + (row << 7);
        #pragma unroll
        for (int q = 0; q < 4; q++) {
            int g = half * 4 + q;
            uint32_t swz = (uint32_t)(g ^ (row & 7));
            CP_ASYNC16(dbase + (swz << 4), src + q * 16);
        }
        CP_COMMIT();
    };

    load_stage(0);
    load_stage(1);
    load_stage(2);

    float acc[2][2][2][4];   // [mt][ntp][sub][quad]
    #pragma unroll
    for (int a = 0; a < 2; a++)
        #pragma unroll
        for (int b2 = 0; b2 < 2; b2++)
            #pragma unroll
            for (int c = 0; c < 2; c++)
                #pragma unroll
                for (int d = 0; d < 4; d++) acc[a][b2][c][d] = 0.0f;

    const int ag = lane >> 4;
    const int bg = (lane >> 3) & 1;
    const int brow_base = wn * 32 + ((lane >> 4) << 3) + (lane & 7);
    const int l7 = lane & 7;
    const int rl = lane >> 2;
    float* stag = (float*)(smem + SM_STAG);   // [o][m] 64x128

    for (int s = 0; s < S; s++) {
        int rem = S - 1 - s;
        if (rem >= 2) CP_WAIT2();
        else if (rem == 1) CP_WAIT1();
        else CP_WAIT0();
        BAR_SYNC(1 + kg);                    // kg-half of stage s visible

        if (s + 3 < S) load_stage(s + 3);

        const int tap = s - 3 * (s / 3);
        const uint32_t awarp = sb + SM_A + (s % NSLOT) * 32768 + (kg << 14)
                             + (wm * 32 + (lane & 15)) * 128;
        const uint32_t wtap = sb + SM_W + tap * 16384;

        // burst 8 independent LDSM, then 16 MMA (x2)
        #pragma unroll
        for (int kp = 0; kp < 2; kp++) {
            uint32_t af[2][2][4];   // [ks][mt]
            uint32_t bf[2][2][4];   // [ks][ntp]
            #pragma unroll
            for (int ks = 0; ks < 2; ks++) {
                int ql = (kp * 2 + ks) * 2 + ag;        // local chunk 0..7
                uint32_t swA = (uint32_t)(ql ^ l7);
                LDSM_X4(af[ks][0][0], af[ks][0][1], af[ks][0][2], af[ks][0][3],
                        awarp + (swA << 4));
                LDSM_X4(af[ks][1][0], af[ks][1][1], af[ks][1][2], af[ks][1][3],
                        awarp + 2048 + (swA << 4));
                int gb = kg * 8 + (kp * 2 + ks) * 2 + bg;
                uint32_t swB = (uint32_t)((gb & 8) | ((gb & 7) ^ l7));
                LDSM_X4(bf[ks][0][0], bf[ks][0][1], bf[ks][0][2], bf[ks][0][3],
                        wtap + brow_base * 256 + (swB << 4));
                LDSM_X4(bf[ks][1][0], bf[ks][1][1], bf[ks][1][2], bf[ks][1][3],
                        wtap + (brow_base + 16) * 256 + (swB << 4));
            }
            #pragma unroll
            for (int ks = 0; ks < 2; ks++) {
                #pragma unroll
                for (int ntp = 0; ntp < 2; ntp++) {
                    MMA_F16(acc[0][ntp][0], af[ks][0], bf[ks][ntp][0], bf[ks][ntp][1]);
                    MMA_F16(acc[0][ntp][1], af[ks][0], bf[ks][ntp][2], bf[ks][ntp][3]);
                    MMA_F16(acc[1][ntp][0], af[ks][1], bf[ks][ntp][0], bf[ks][ntp][1]);
                    MMA_F16(acc[1][ntp][1], af[ks][1], bf[ks][ntp][2], bf[ks][ntp][3]);
                }
            }
        }

        // ---- after tap 2: kg1 stages partials, kg0 reduces + stores ----
        if (tap == 2) {
            int tile = cta + (s / 3) * GRID_P;
            int b = tile >> 3, m0 = (tile & 7) << 7;
            float* ob = out + (((size_t)b * COUT) << 10);
            __syncthreads();   // stag WAR: kg0 done reading previous tile
            if (kg == 1) {
                #pragma unroll
                for (int mt = 0; mt < 2; mt++) {
                    int m = wm * 32 + mt * 16 + rl;
                    #pragma unroll
                    for (int ntp = 0; ntp < 2; ntp++)
                        #pragma unroll
                        for (int sub = 0; sub < 2; sub++) {
                            int o = wn * 32 + ntp * 16 + sub * 8 + ocl;
                            float* q = &acc[mt][ntp][sub][0];
                            stag[o * 128 + m]           = q[0];
                            stag[(o + 1) * 128 + m]     = q[1];
                            stag[o * 128 + m + 8]       = q[2];
                            stag[(o + 1) * 128 + m + 8] = q[3];
                            q[0] = q[1] = q[2] = q[3] = 0.0f;
                        }
                }
                // zero column m=0 (only tiles that own m0 == 0)
                if (m0 == 0 && lane < 8) {
                    int o = (w - 8) * 8 + lane;
                    ob[(size_t)o << 10] = 0.0f;
                }
            }
            __syncthreads();   // kg1 partials visible to kg0
            if (kg == 0) {
                #pragma unroll
                for (int mt = 0; mt < 2; mt++) {
                    int m = wm * 32 + mt * 16 + rl;
                    int gmb = m0 + m;
                    #pragma unroll
                    for (int ntp = 0; ntp < 2; ntp++)
                        #pragma unroll
                        for (int sub = 0; sub < 2; sub++) {
                            int o = wn * 32 + ntp * 16 + sub * 8 + ocl;
                            float* p0 = ob + (((size_t)o) << 10) + 1;
                            float* p1 = ob + (((size_t)(o + 1)) << 10) + 1;
                            float* q = &acc[mt][ntp][sub][0];
                            float v0 = q[0] + stag[o * 128 + m]           + bv[ntp][sub][0];
                            float v1 = q[1] + stag[(o + 1) * 128 + m]     + bv[ntp][sub][1];
                            float v2 = q[2] + stag[o * 128 + m + 8]       + bv[ntp][sub][0];
                            float v3 = q[3] + stag[(o + 1) * 128 + m + 8] + bv[ntp][sub][1];
                            if (gmb < M_) { p0[gmb] = v0; p1[gmb] = v1; }
                            if (gmb + 8 < M_) { p0[gmb + 8] = v2; p1[gmb + 8] = v3; }
                            q[0] = q[1] = q[2] = q[3] = 0.0f;
                        }
                }
            }
        }
    }
}

// ---------------- kernel 4: optional index tail (mode 1/2 only) ------------
__global__ void tail_kernel(const void* __restrict__ idx_raw,
                            float* __restrict__ out, int mode) {
    int i = blockIdx.x * 256 + threadIdx.x;
    const int is64 = g_idx_is64;
    const int* i32 = (const int*)idx_raw;
    const long long* i64 = (const long long*)idx_raw;
    if (i < B_ * M3) {
        long long v = is64 ? i64[i] : (long long)i32[i];
        if (mode == 1) {
            out[(size_t)B_ * COUT * OUTW + i] = (float)v;
        } else if (mode == 2) {
            ((long long*)out)[(size_t)(B_ * COUT * OUTW) / 2 + i] = v;
        }
    }
}

// ---------------------------------------------------------------------------
extern "C" void kernel_launch(void* const* d_in, const int* in_sizes, int n_in,
                              void* d_out, int out_size) {
    const float* trees = nullptr;
    const void* indexes = nullptr;
    const float* W = nullptr;
    const float* bias = nullptr;
    for (int i = 0; i < n_in; i++) {
        switch (in_sizes[i]) {
            case B_ * CIN * NPTS: trees   = (const float*)d_in[i]; break;
            case B_ * M3:         indexes = d_in[i];               break;
            case COUT * CIN * 3:  W       = (const float*)d_in[i]; break;
            case COUT:            bias    = (const float*)d_in[i]; break;
        }
    }
    float* out = (float*)d_out;

    cudaFuncSetAttribute(convtree_persist_kernel,
                         cudaFuncAttributeMaxDynamicSharedMemorySize, SMEM_TOTAL);

    detect_kernel<<<1, 256>>>((const int*)indexes);
    transpose_half_kernel<<<dim3(NPTS / 64, CIN / 64, B_), 256>>>(trees);
    wprep_kernel<<<(3 * 64 * 128 + 255) / 256, 256>>>(W);
    convtree_persist_kernel<<<GRID_P, 512, SMEM_TOTAL>>>(indexes, bias, out);

    long long R = (long long)B_ * COUT * OUTW;
    long long I = (long long)B_ * M3;
    int mode = 0;
    if ((long long)out_size >= R + 2 * I)      mode = 2;
    else if ((long long)out_size >= R + I)     mode = 1;
    if (mode != 0)
        tail_kernel<<<(B_ * M3 + 255) / 256, 256>>>(indexes, out, mode);
}